// round 4
// baseline (speedup 1.0000x reference)
#include <cuda_runtime.h>
#include <math.h>

#define NN 50000
#define NE 600000
#define CH 128
#define MB 16           // nodes per GEMM block
#define SW_PITCH 132    // padded smem pitch (floats) -> conflict-free float4 reads

// ---- scratch (__device__ globals; no allocations allowed) ----
__device__ int   g_degi[NN];
__device__ float g_dinv[NN];
__device__ float g_h[(size_t)NN * CH];
__device__ int   g_is64;

// edge-index fetch that works for int32 or int64 buffers
__device__ __forceinline__ int fetch_idx(const void* ei, long long pos, int is64) {
    if (is64) return (int)__ldg(&((const long long*)ei)[pos]);
    return __ldg(&((const int*)ei)[pos]);
}

// ------------------------------------------------------------ dtype probe ----
// int64 little-endian values < 2^31 have all odd 32-bit words == 0.
// For int32 indices uniform in [0,50000), 64 consecutive zeros has
// probability ~(1/50000)^64 — impossible in practice.
__global__ void k_detect(const int* __restrict__ ei32) {
    if (threadIdx.x == 0 && blockIdx.x == 0) {
        int is64 = 1;
        #pragma unroll 1
        for (int k = 0; k < 64; k++)
            if (ei32[2 * k + 1] != 0) { is64 = 0; break; }
        g_is64 = is64;
    }
}

// ---------------------------------------------------------------- degree ----
__global__ void k_deg_init() {
    int i = blockIdx.x * blockDim.x + threadIdx.x;
    if (i < NN) g_degi[i] = 1;   // self-loop contributes 1
}

__global__ void k_deg_count(const void* __restrict__ ei) {
    int e = blockIdx.x * blockDim.x + threadIdx.x;
    if (e >= NE) return;
    const int is64 = g_is64;
    int col = fetch_idx(ei, (long long)NE + e, is64);   // target i
    if ((unsigned)col < NN) atomicAdd(&g_degi[col], 1);
}

__global__ void k_dinv() {
    int i = blockIdx.x * blockDim.x + threadIdx.x;
    if (i < NN) g_dinv[i] = rsqrtf((float)g_degi[i]);
}

// ------------------------------------------------- h = x @ W^T + self-loop ----
// 128 threads/block; thread t owns output channel t; block computes MB nodes.
// Per k4 step: 1 LDS.128 (W row slice) + MB LDS.128 broadcast (x) + 4*MB FFMA.
__global__ void __launch_bounds__(128) k_gemm(const float* __restrict__ x,
                                              const float* __restrict__ W,
                                              float* __restrict__ agg) {
    extern __shared__ float smem[];
    float* sW = smem;                    // [128][SW_PITCH]
    float* sx = smem + CH * SW_PITCH;    // [MB][SW_PITCH]
    const int t = threadIdx.x;

    #pragma unroll 8
    for (int o = 0; o < CH; o++)
        sW[o * SW_PITCH + t] = W[o * CH + t];

    const int node0 = blockIdx.x * MB;
    #pragma unroll
    for (int m = 0; m < MB; m++)
        sx[m * SW_PITCH + t] = x[(size_t)(node0 + m) * CH + t];
    __syncthreads();

    float acc[MB];
    #pragma unroll
    for (int m = 0; m < MB; m++) acc[m] = 0.0f;

    #pragma unroll 4
    for (int k4 = 0; k4 < CH; k4 += 4) {
        float4 w = *(const float4*)&sW[t * SW_PITCH + k4];
        #pragma unroll
        for (int m = 0; m < MB; m++) {
            float4 xv = *(const float4*)&sx[m * SW_PITCH + k4];
            acc[m] = fmaf(xv.x, w.x, acc[m]);
            acc[m] = fmaf(xv.y, w.y, acc[m]);
            acc[m] = fmaf(xv.z, w.z, acc[m]);
            acc[m] = fmaf(xv.w, w.w, acc[m]);
        }
    }

    #pragma unroll
    for (int m = 0; m < MB; m++) {
        const int node = node0 + m;
        const float di = g_dinv[node];
        g_h[(size_t)node * CH + t] = acc[m];
        // self-loop message h[i]*dinv[i]^2 initializes agg (overwrites poison)
        agg[(size_t)node * CH + t] = acc[m] * di * di;
    }
}

// ----------------------------------------------------------- edge scatter ----
// one warp per edge; lane handles 4 channels; vectorized global reduction
__global__ void __launch_bounds__(512) k_scatter(const void* __restrict__ ei,
                                                 float* __restrict__ agg) {
    const int gw = (blockIdx.x * blockDim.x + threadIdx.x) >> 5;
    const int lane = threadIdx.x & 31;
    if (gw >= NE) return;
    const int is64 = g_is64;
    const int row = fetch_idx(ei, gw, is64);                 // source j
    const int col = fetch_idx(ei, (long long)NE + gw, is64); // target i
    if ((unsigned)row >= NN || (unsigned)col >= NN) return;
    const float norm = g_dinv[row] * g_dinv[col];
    float4 v = *(const float4*)(g_h + (size_t)row * CH + lane * 4);
    v.x *= norm; v.y *= norm; v.z *= norm; v.w *= norm;
    float* dst = agg + (size_t)col * CH + lane * 4;
    asm volatile("red.global.add.v4.f32 [%0], {%1, %2, %3, %4};"
                 :: "l"(dst), "f"(v.x), "f"(v.y), "f"(v.z), "f"(v.w)
                 : "memory");
}

// -------------------------------------------------------- epilogue (silu) ----
__global__ void k_final(float* __restrict__ out, const float* __restrict__ b) {
    const int i = blockIdx.x * blockDim.x + threadIdx.x;   // index over float4s
    if (i >= NN * (CH / 4)) return;
    const int node = i >> 5;          // 32 float4s per node
    const int c4 = (i & 31) << 2;
    const float di = g_dinv[node];
    float4 v = ((float4*)out)[i];
    float4 bb = *(const float4*)(b + c4);
    float y;
    y = v.x * di + bb.x; v.x = y / (1.0f + __expf(-y));
    y = v.y * di + bb.y; v.y = y / (1.0f + __expf(-y));
    y = v.z * di + bb.z; v.z = y / (1.0f + __expf(-y));
    y = v.w * di + bb.w; v.w = y / (1.0f + __expf(-y));
    ((float4*)out)[i] = v;
}

// ------------------------------------------------------------------ launch ----
extern "C" void kernel_launch(void* const* d_in, const int* in_sizes, int n_in,
                              void* d_out, int out_size) {
    const float* x  = (const float*)d_in[0];
    const void*  ei = d_in[1];
    const float* W  = (const float*)d_in[2];
    const float* b  = (const float*)d_in[3];
    float* out = (float*)d_out;

    (void)in_sizes; (void)n_in; (void)out_size;

    k_detect<<<1, 32>>>((const int*)ei);
    k_deg_init<<<(NN + 255) / 256, 256>>>();
    k_deg_count<<<(NE + 255) / 256, 256>>>(ei);
    k_dinv<<<(NN + 255) / 256, 256>>>();

    const int smem_bytes = (CH * SW_PITCH + MB * SW_PITCH) * (int)sizeof(float); // 76032
    cudaFuncSetAttribute(k_gemm, cudaFuncAttributeMaxDynamicSharedMemorySize, smem_bytes);
    k_gemm<<<NN / MB, 128, smem_bytes>>>(x, W, out);

    k_scatter<<<(NE * 32 + 511) / 512, 512>>>(ei, out);

    k_final<<<(NN * (CH / 4) + 255) / 256, 256>>>(out, b);
}

// round 7
// speedup vs baseline: 1.3117x; 1.3117x over previous
#include <cuda_runtime.h>
#include <math.h>

#define NN   50000
#define NE   600000
#define CH   128
#define MB   16          // nodes per GEMM block
#define SW_PITCH 132     // padded smem pitch (floats)
#define NBLK 196         // ceil(NN/256) scan blocks

// ---- scratch (__device__ globals; allocations forbidden) ----
__device__ int   g_cnt[NN];          // in-degree counts (zero-invariant across calls)
__device__ int   g_incl[NBLK * 256]; // block-local inclusive scan
__device__ int   g_bsum[NBLK];       // per-block totals
__device__ int   g_off[NN];          // CSR begin
__device__ int   g_end[NN];          // CSR end
__device__ int   g_cur[NN];          // fill cursors
__device__ int   g_src[NE];          // CSR source lists
__device__ float g_dinv[NN];
__device__ float g_h[(size_t)NN * CH];

// ---- dtype handling: edge_index may be int32 or int64 ----
// int64 LE values < 2^31 have all odd 32-bit words zero. Probe 16 odd words
// (2 cache lines, L1-resident) — per-thread, deterministic, no extra kernel.
__device__ __forceinline__ int detect64(const int* ei32) {
    int z = 0;
    #pragma unroll
    for (int k = 0; k < 16; k++) z |= __ldg(&ei32[2 * k + 1]);
    return z == 0;
}
__device__ __forceinline__ int fetch_idx(const void* ei, long long pos, int is64) {
    if (is64) return (int)__ldg(&((const long long*)ei)[pos]);
    return __ldg(&((const int*)ei)[pos]);
}

// --------------------------------------------------- 1) in-degree counts ----
__global__ void __launch_bounds__(256) k_count(const void* __restrict__ ei) {
    int e = blockIdx.x * blockDim.x + threadIdx.x;
    if (e >= NE) return;
    const int is64 = detect64((const int*)ei);
    int col = fetch_idx(ei, (long long)NE + e, is64);
    if ((unsigned)col < NN) atomicAdd(&g_cnt[col], 1);
}

// ------------------------------------- 2) block-local inclusive scan ----
__global__ void __launch_bounds__(256) k_scanA() {
    __shared__ int wsum[8];
    const int t = threadIdx.x, lane = t & 31, w = t >> 5;
    const int i = blockIdx.x * 256 + t;
    int c = (i < NN) ? g_cnt[i] : 0;
    if (i < NN) g_cnt[i] = 0;                 // restore zero-invariant
    int incl = c;
    #pragma unroll
    for (int o = 1; o < 32; o <<= 1) {
        int v = __shfl_up_sync(~0u, incl, o);
        if (lane >= o) incl += v;
    }
    if (lane == 31) wsum[w] = incl;
    __syncthreads();
    if (w == 0) {
        int v = (lane < 8) ? wsum[lane] : 0;
        #pragma unroll
        for (int o = 1; o < 8; o <<= 1) {
            int u = __shfl_up_sync(~0u, v, o);
            if (lane >= o) v += u;
        }
        if (lane < 8) wsum[lane] = v;
    }
    __syncthreads();
    incl += (w > 0) ? wsum[w - 1] : 0;
    g_incl[i] = incl;
    if (t == 255) g_bsum[blockIdx.x] = incl;
}

// --------- 3) offsets: each block reduces prior block sums, finalizes ----
__global__ void __launch_bounds__(256) k_scanC() {
    __shared__ int red[8];
    __shared__ int s_boff;
    const int t = threadIdx.x, lane = t & 31, w = t >> 5;
    int v = (t < blockIdx.x) ? g_bsum[t] : 0;   // blockIdx.x <= 195 < 256
    #pragma unroll
    for (int o = 16; o; o >>= 1) v += __shfl_down_sync(~0u, v, o);
    if (lane == 0) red[w] = v;
    __syncthreads();
    if (t == 0) {
        int s = 0;
        #pragma unroll
        for (int k = 0; k < 8; k++) s += red[k];
        s_boff = s;
    }
    __syncthreads();
    const int i = blockIdx.x * 256 + t;
    if (i >= NN) return;
    const int incl = g_incl[i];
    const int excl = (t > 0) ? g_incl[i - 1] : 0;   // block-local exclusive
    const int off  = s_boff + excl;
    const int cnt  = incl - excl;
    g_off[i]  = off;
    g_end[i]  = off + cnt;
    g_cur[i]  = off;
    g_dinv[i] = rsqrtf((float)cnt + 1.0f);          // +1 self loop
}

// ---------------------------------------------------- 4) fill CSR lists ----
__global__ void __launch_bounds__(256) k_fill(const void* __restrict__ ei) {
    int e = blockIdx.x * blockDim.x + threadIdx.x;
    if (e >= NE) return;
    const int is64 = detect64((const int*)ei);
    int row = fetch_idx(ei, e, is64);
    int col = fetch_idx(ei, (long long)NE + e, is64);
    if ((unsigned)col >= NN || (unsigned)row >= NN) return;
    int pos = atomicAdd(&g_cur[col], 1);
    g_src[pos] = row;
}

// --------------------------------------------------------- 5) h = x W^T ----
__global__ void __launch_bounds__(128) k_gemm(const float* __restrict__ x,
                                              const float* __restrict__ W) {
    extern __shared__ float smem[];
    float* sW = smem;                    // [128][SW_PITCH]
    float* sx = smem + CH * SW_PITCH;    // [MB][SW_PITCH]
    const int t = threadIdx.x;

    #pragma unroll 8
    for (int o = 0; o < CH; o++)
        sW[o * SW_PITCH + t] = W[o * CH + t];

    const int node0 = blockIdx.x * MB;
    #pragma unroll
    for (int m = 0; m < MB; m++)
        sx[m * SW_PITCH + t] = x[(size_t)(node0 + m) * CH + t];
    __syncthreads();

    float acc[MB];
    #pragma unroll
    for (int m = 0; m < MB; m++) acc[m] = 0.0f;

    #pragma unroll 4
    for (int k4 = 0; k4 < CH; k4 += 4) {
        float4 w = *(const float4*)&sW[t * SW_PITCH + k4];
        #pragma unroll
        for (int m = 0; m < MB; m++) {
            float4 xv = *(const float4*)&sx[m * SW_PITCH + k4];
            acc[m] = fmaf(xv.x, w.x, acc[m]);
            acc[m] = fmaf(xv.y, w.y, acc[m]);
            acc[m] = fmaf(xv.z, w.z, acc[m]);
            acc[m] = fmaf(xv.w, w.w, acc[m]);
        }
    }

    #pragma unroll
    for (int m = 0; m < MB; m++)
        g_h[(size_t)(node0 + m) * CH + t] = acc[m];
}

// ------------------- 6) gather + fused epilogue (self, norm, bias, silu) ----
// warp per node; lane owns 4 channels (one LDG.128 per edge covers the row)
__global__ void __launch_bounds__(256) k_gather(const float* __restrict__ b,
                                                float* __restrict__ out) {
    const int node = (blockIdx.x * blockDim.x + threadIdx.x) >> 5;
    const int lane = threadIdx.x & 31;
    if (node >= NN) return;
    const int c4 = lane * 4;
    const int beg = g_off[node], end = g_end[node];

    float4 acc = make_float4(0.f, 0.f, 0.f, 0.f);
    int e = beg;
    int src_n = (e < end) ? __ldg(&g_src[e]) : 0;
    float d_n  = (e < end) ? __ldg(&g_dinv[src_n]) : 0.f;
    for (; e < end; e++) {
        const int src = src_n;
        const float d = d_n;
        if (e + 1 < end) {                  // software prefetch next edge
            src_n = __ldg(&g_src[e + 1]);
            d_n   = __ldg(&g_dinv[src_n]);
        }
        float4 v = *(const float4*)(g_h + (size_t)src * CH + c4);
        acc.x = fmaf(v.x, d, acc.x);
        acc.y = fmaf(v.y, d, acc.y);
        acc.z = fmaf(v.z, d, acc.z);
        acc.w = fmaf(v.w, d, acc.w);
    }

    const float di  = g_dinv[node];
    const float di2 = di * di;
    float4 hv = *(const float4*)(g_h + (size_t)node * CH + c4);
    float4 bb = *(const float4*)(b + c4);
    float y;
    y = fmaf(acc.x + hv.x * di, di2, bb.x); acc.x = y / (1.0f + __expf(-y));
    y = fmaf(acc.y + hv.y * di, di2, bb.y); acc.y = y / (1.0f + __expf(-y));
    y = fmaf(acc.z + hv.z * di, di2, bb.z); acc.z = y / (1.0f + __expf(-y));
    y = fmaf(acc.w + hv.w * di, di2, bb.w); acc.w = y / (1.0f + __expf(-y));
    *(float4*)(out + (size_t)node * CH + c4) = acc;
}

// ------------------------------------------------------------------ launch ----
extern "C" void kernel_launch(void* const* d_in, const int* in_sizes, int n_in,
                              void* d_out, int out_size) {
    const float* x  = (const float*)d_in[0];
    const void*  ei = d_in[1];
    const float* W  = (const float*)d_in[2];
    const float* b  = (const float*)d_in[3];
    float* out = (float*)d_out;
    (void)in_sizes; (void)n_in; (void)out_size;

    k_count<<<(NE + 255) / 256, 256>>>(ei);          // 1
    k_scanA<<<NBLK, 256>>>();                        // 2
    k_scanC<<<NBLK, 256>>>();                        // 3
    k_fill<<<(NE + 255) / 256, 256>>>(ei);           // 4

    const int smem_bytes = (CH * SW_PITCH + MB * SW_PITCH) * (int)sizeof(float);
    cudaFuncSetAttribute(k_gemm, cudaFuncAttributeMaxDynamicSharedMemorySize, smem_bytes);
    k_gemm<<<NN / MB, 128, smem_bytes>>>(x, W);      // 5

    k_gather<<<(NN * 32 + 255) / 256, 256>>>(b, out); // 6  (ncu -s 5 captures this)
}

// round 8
// speedup vs baseline: 1.5177x; 1.1570x over previous
#include <cuda_runtime.h>
#include <math.h>

#define NN   50000
#define NE   600000
#define CH   128
#define NBT  64          // nodes per GEMM block (4 warps x 16 nodes)
#define SW_PITCH 132     // padded smem pitch for W (floats)
#define NBLK 196         // ceil(NN/256) scan blocks
#define EPT  4           // edges per thread in count/fill (MLP)

// ---- scratch (__device__ globals; allocations forbidden) ----
__device__ int   g_cnt[NN];          // in-degree counts (zero-invariant across calls)
__device__ int   g_incl[NBLK * 256]; // block-local inclusive scan
__device__ int   g_bsum[NBLK];       // per-block totals
__device__ int   g_off[NN];          // CSR begin
__device__ int   g_end[NN];          // CSR end
__device__ int   g_cur[NN];          // fill cursors
__device__ int   g_src[NE];          // CSR source lists
__device__ float g_dinv[NN];
__device__ float g_h[(size_t)NN * CH];

// ---- packed fp32x2 helpers (FFMA2 path; ptxas never emits this from C++) ----
#define FMA2(d, a, b, c) \
    asm("fma.rn.f32x2 %0, %1, %2, %3;" : "=l"(d) : "l"(a), "l"(b), "l"(c))
#define PACK2(out, lo, hi) \
    asm("mov.b64 %0, {%1, %2};" : "=l"(out) : "r"(lo), "r"(hi))
#define UNPACK2(lo, hi, in) \
    asm("mov.b64 {%0, %1}, %2;" : "=r"(lo), "=r"(hi) : "l"(in))

// ---- dtype handling: edge_index may be int32 or int64 ----
// int64 LE values < 2^31 have all odd 32-bit words zero. Probe 16 odd words.
__device__ __forceinline__ int detect64(const int* ei32) {
    int z = 0;
    #pragma unroll
    for (int k = 0; k < 16; k++) z |= __ldg(&ei32[2 * k + 1]);
    return z == 0;
}
__device__ __forceinline__ int fetch_idx(const void* ei, long long pos, int is64) {
    if (is64) return (int)__ldg(&((const long long*)ei)[pos]);
    return __ldg(&((const int*)ei)[pos]);
}

// --------------------------------------------- 1) in-degree counts (MLP=4) ----
__global__ void __launch_bounds__(256) k_count(const void* __restrict__ ei) {
    const int base = blockIdx.x * blockDim.x + threadIdx.x;
    const int stride = gridDim.x * blockDim.x;
    const int is64 = detect64((const int*)ei);
    #pragma unroll
    for (int i = 0; i < EPT; i++) {
        int e = base + i * stride;
        if (e < NE) {
            int col = fetch_idx(ei, (long long)NE + e, is64);
            if ((unsigned)col < NN) atomicAdd(&g_cnt[col], 1);
        }
    }
}

// ------------------------------------- 2) block-local inclusive scan ----
__global__ void __launch_bounds__(256) k_scanA() {
    __shared__ int wsum[8];
    const int t = threadIdx.x, lane = t & 31, w = t >> 5;
    const int i = blockIdx.x * 256 + t;
    int c = (i < NN) ? g_cnt[i] : 0;
    if (i < NN) g_cnt[i] = 0;                 // restore zero-invariant
    int incl = c;
    #pragma unroll
    for (int o = 1; o < 32; o <<= 1) {
        int v = __shfl_up_sync(~0u, incl, o);
        if (lane >= o) incl += v;
    }
    if (lane == 31) wsum[w] = incl;
    __syncthreads();
    if (w == 0) {
        int v = (lane < 8) ? wsum[lane] : 0;
        #pragma unroll
        for (int o = 1; o < 8; o <<= 1) {
            int u = __shfl_up_sync(~0u, v, o);
            if (lane >= o) v += u;
        }
        if (lane < 8) wsum[lane] = v;
    }
    __syncthreads();
    incl += (w > 0) ? wsum[w - 1] : 0;
    g_incl[i] = incl;
    if (t == 255) g_bsum[blockIdx.x] = incl;
}

// --------- 3) offsets: each block reduces prior block sums, finalizes ----
__global__ void __launch_bounds__(256) k_scanC() {
    __shared__ int red[8];
    __shared__ int s_boff;
    const int t = threadIdx.x, lane = t & 31, w = t >> 5;
    int v = (t < blockIdx.x) ? g_bsum[t] : 0;   // blockIdx.x <= 195 < 256
    #pragma unroll
    for (int o = 16; o; o >>= 1) v += __shfl_down_sync(~0u, v, o);
    if (lane == 0) red[w] = v;
    __syncthreads();
    if (t == 0) {
        int s = 0;
        #pragma unroll
        for (int k = 0; k < 8; k++) s += red[k];
        s_boff = s;
    }
    __syncthreads();
    const int i = blockIdx.x * 256 + t;
    if (i >= NN) return;
    const int incl = g_incl[i];
    const int excl = (t > 0) ? g_incl[i - 1] : 0;   // block-local exclusive
    const int off  = s_boff + excl;
    const int cnt  = incl - excl;
    g_off[i]  = off;
    g_end[i]  = off + cnt;
    g_cur[i]  = off;
    g_dinv[i] = rsqrtf((float)cnt + 1.0f);          // +1 self loop
}

// ---------------------------------------------- 4) fill CSR lists (MLP=4) ----
__global__ void __launch_bounds__(256) k_fill(const void* __restrict__ ei) {
    const int base = blockIdx.x * blockDim.x + threadIdx.x;
    const int stride = gridDim.x * blockDim.x;
    const int is64 = detect64((const int*)ei);
    #pragma unroll
    for (int i = 0; i < EPT; i++) {
        int e = base + i * stride;
        if (e < NE) {
            int row = fetch_idx(ei, e, is64);
            int col = fetch_idx(ei, (long long)NE + e, is64);
            if ((unsigned)col < NN && (unsigned)row < NN) {
                int pos = atomicAdd(&g_cur[col], 1);
                g_src[pos] = row;
            }
        }
    }
}

// ----------------------------------------- 5) h = x W^T  (packed FFMA2) ----
// 128 threads = 4 warps; warp w owns nodes [node0+16w, +16) as 8 node-pairs.
// Lane owns 4 channels: lane, lane+32, lane+64, lane+96.
// x stored pair-interleaved in smem: sxp[pair][k] = (x_{2p}[k], x_{2p+1}[k]).
// Per k4 per thread: 4 LDS.128 (w) + 16 LDS.128 (x pairs) + 16 packs + 128 FMA2.
__global__ void __launch_bounds__(128) k_gemm(const float* __restrict__ x,
                                              const float* __restrict__ W) {
    extern __shared__ float smem[];
    float* sW  = smem;                       // [128][SW_PITCH]
    float* sxp = smem + CH * SW_PITCH;       // [32 pairs][CH][2]
    const int t = threadIdx.x;
    const int lane = t & 31, wid = t >> 5;
    const int node0 = blockIdx.x * NBT;

    #pragma unroll 8
    for (int o = 0; o < CH; o++)
        sW[o * SW_PITCH + t] = W[o * CH + t];

    #pragma unroll 4
    for (int m = 0; m < NBT; m++) {
        const int node = node0 + m;
        const float v = (node < NN) ? x[(size_t)node * CH + t] : 0.0f;
        sxp[((m >> 1) * CH + t) * 2 + (m & 1)] = v;
    }
    __syncthreads();

    unsigned long long acc2[4][8];
    #pragma unroll
    for (int c = 0; c < 4; c++)
        #pragma unroll
        for (int p = 0; p < 8; p++) acc2[c][p] = 0ull;

    const float* w0 = &sW[lane * SW_PITCH];
    const float* w1 = &sW[(lane + 32) * SW_PITCH];
    const float* w2 = &sW[(lane + 64) * SW_PITCH];
    const float* w3 = &sW[(lane + 96) * SW_PITCH];
    const float* xbase = &sxp[(wid * 8) * CH * 2];

    #pragma unroll 2
    for (int k4 = 0; k4 < CH; k4 += 4) {
        float4 wv[4];
        wv[0] = *(const float4*)(w0 + k4);
        wv[1] = *(const float4*)(w1 + k4);
        wv[2] = *(const float4*)(w2 + k4);
        wv[3] = *(const float4*)(w3 + k4);
        unsigned long long wp[4][4];
        #pragma unroll
        for (int c = 0; c < 4; c++) {
            PACK2(wp[c][0], __float_as_uint(wv[c].x), __float_as_uint(wv[c].x));
            PACK2(wp[c][1], __float_as_uint(wv[c].y), __float_as_uint(wv[c].y));
            PACK2(wp[c][2], __float_as_uint(wv[c].z), __float_as_uint(wv[c].z));
            PACK2(wp[c][3], __float_as_uint(wv[c].w), __float_as_uint(wv[c].w));
        }
        #pragma unroll
        for (int p = 0; p < 8; p++) {
            const float* xb = xbase + (p * CH + k4) * 2;
            ulonglong2 xk01 = *(const ulonglong2*)(xb);      // pairs for k4, k4+1
            ulonglong2 xk23 = *(const ulonglong2*)(xb + 4);  // pairs for k4+2, k4+3
            #pragma unroll
            for (int c = 0; c < 4; c++) {
                FMA2(acc2[c][p], xk01.x, wp[c][0], acc2[c][p]);
                FMA2(acc2[c][p], xk01.y, wp[c][1], acc2[c][p]);
                FMA2(acc2[c][p], xk23.x, wp[c][2], acc2[c][p]);
                FMA2(acc2[c][p], xk23.y, wp[c][3], acc2[c][p]);
            }
        }
    }

    #pragma unroll
    for (int c = 0; c < 4; c++) {
        const int ch = lane + 32 * c;
        #pragma unroll
        for (int p = 0; p < 8; p++) {
            unsigned int lo, hi;
            UNPACK2(lo, hi, acc2[c][p]);
            const int n0 = node0 + wid * 16 + 2 * p;
            if (n0 < NN)     g_h[(size_t)n0 * CH + ch]       = __uint_as_float(lo);
            if (n0 + 1 < NN) g_h[(size_t)(n0 + 1) * CH + ch] = __uint_as_float(hi);
        }
    }
}

// ------------------- 6) gather + fused epilogue (self, norm, bias, silu) ----
// warp per node; lane owns 4 channels; 2-edge unroll with dual accumulators
__global__ void __launch_bounds__(256) k_gather(const float* __restrict__ b,
                                                float* __restrict__ out) {
    const int node = (blockIdx.x * blockDim.x + threadIdx.x) >> 5;
    const int lane = threadIdx.x & 31;
    if (node >= NN) return;
    const int c4 = lane * 4;
    const int beg = g_off[node], end = g_end[node];

    float4 a0 = make_float4(0.f, 0.f, 0.f, 0.f);
    float4 a1 = make_float4(0.f, 0.f, 0.f, 0.f);
    int e = beg;
    for (; e + 2 <= end; e += 2) {
        const int s0 = __ldg(&g_src[e]);
        const int s1 = __ldg(&g_src[e + 1]);
        const float d0 = __ldg(&g_dinv[s0]);
        const float d1 = __ldg(&g_dinv[s1]);
        float4 v0 = *(const float4*)(g_h + (size_t)s0 * CH + c4);
        float4 v1 = *(const float4*)(g_h + (size_t)s1 * CH + c4);
        a0.x = fmaf(v0.x, d0, a0.x); a1.x = fmaf(v1.x, d1, a1.x);
        a0.y = fmaf(v0.y, d0, a0.y); a1.y = fmaf(v1.y, d1, a1.y);
        a0.z = fmaf(v0.z, d0, a0.z); a1.z = fmaf(v1.z, d1, a1.z);
        a0.w = fmaf(v0.w, d0, a0.w); a1.w = fmaf(v1.w, d1, a1.w);
    }
    if (e < end) {
        const int s0 = __ldg(&g_src[e]);
        const float d0 = __ldg(&g_dinv[s0]);
        float4 v0 = *(const float4*)(g_h + (size_t)s0 * CH + c4);
        a0.x = fmaf(v0.x, d0, a0.x);
        a0.y = fmaf(v0.y, d0, a0.y);
        a0.z = fmaf(v0.z, d0, a0.z);
        a0.w = fmaf(v0.w, d0, a0.w);
    }
    a0.x += a1.x; a0.y += a1.y; a0.z += a1.z; a0.w += a1.w;

    const float di  = g_dinv[node];
    const float di2 = di * di;
    float4 hv = *(const float4*)(g_h + (size_t)node * CH + c4);
    float4 bb = *(const float4*)(b + c4);
    float y;
    y = fmaf(a0.x + hv.x * di, di2, bb.x); a0.x = y / (1.0f + __expf(-y));
    y = fmaf(a0.y + hv.y * di, di2, bb.y); a0.y = y / (1.0f + __expf(-y));
    y = fmaf(a0.z + hv.z * di, di2, bb.z); a0.z = y / (1.0f + __expf(-y));
    y = fmaf(a0.w + hv.w * di, di2, bb.w); a0.w = y / (1.0f + __expf(-y));
    *(float4*)(out + (size_t)node * CH + c4) = a0;
}

// ------------------------------------------------------------------ launch ----
extern "C" void kernel_launch(void* const* d_in, const int* in_sizes, int n_in,
                              void* d_out, int out_size) {
    const float* x  = (const float*)d_in[0];
    const void*  ei = d_in[1];
    const float* W  = (const float*)d_in[2];
    const float* b  = (const float*)d_in[3];
    float* out = (float*)d_out;
    (void)in_sizes; (void)n_in; (void)out_size;

    const int eb = (NE + 256 * EPT - 1) / (256 * EPT);   // 586 blocks
    k_count<<<eb, 256>>>(ei);                            // 1
    k_scanA<<<NBLK, 256>>>();                            // 2
    k_scanC<<<NBLK, 256>>>();                            // 3
    k_fill<<<eb, 256>>>(ei);                             // 4

    const int smem_bytes = (CH * SW_PITCH + (NBT / 2) * CH * 2) * (int)sizeof(float); // 100352
    cudaFuncSetAttribute(k_gemm, cudaFuncAttributeMaxDynamicSharedMemorySize, smem_bytes);
    k_gemm<<<(NN + NBT - 1) / NBT, 128, smem_bytes>>>(x, W);  // 5

    k_gather<<<(NN * 32 + 255) / 256, 256>>>(b, out);    // 6
}

// round 16
// speedup vs baseline: 1.5946x; 1.0507x over previous
#include <cuda_runtime.h>
#include <cuda_fp16.h>
#include <math.h>

#define NN   50000
#define NE   600000
#define CH   128
#define NBT  64          // nodes per GEMM block (4 warps x 16 nodes)
#define SW_PITCH 132     // padded smem pitch for W (floats)
#define NBLK 196         // ceil(NN/256) scan blocks
#define EPT  2           // edges per thread in count/fill (MLP=2 at ~full wave)

// ---- scratch (__device__ globals; allocations forbidden) ----
__device__ int    g_cnt[NN];          // in-degree counts (zero-invariant)
__device__ int    g_incl[NBLK * 256]; // block-local inclusive scan
__device__ int    g_bsum[NBLK];       // per-block totals
__device__ int    g_off[NN];          // CSR begin
__device__ int    g_end[NN];          // CSR end
__device__ int    g_cur[NN];          // fill cursors
__device__ int    g_src[NE];          // CSR source lists
__device__ float  g_dinv[NN];
__device__ __half g_hh[(size_t)NN * CH];   // h = xW^T in fp16 (message payload)

// ---- packed fp32x2 helpers (FFMA2; ptxas never emits from C++) ----
#define FMA2(d, a, b, c) \
    asm("fma.rn.f32x2 %0, %1, %2, %3;" : "=l"(d) : "l"(a), "l"(b), "l"(c))
#define PACK2(out, lo, hi) \
    asm("mov.b64 %0, {%1, %2};" : "=l"(out) : "r"(lo), "r"(hi))
#define UNPACK2(lo, hi, in) \
    asm("mov.b64 {%0, %1}, %2;" : "=r"(lo), "=r"(hi) : "l"(in))

// ---- dtype handling: edge_index may be int32 or int64 ----
__device__ __forceinline__ int detect64(const int* ei32) {
    int z = 0;
    #pragma unroll
    for (int k = 0; k < 16; k++) z |= __ldg(&ei32[2 * k + 1]);
    return z == 0;
}
__device__ __forceinline__ int fetch_idx(const void* ei, long long pos, int is64) {
    if (is64) return (int)__ldg(&((const long long*)ei)[pos]);
    return __ldg(&((const int*)ei)[pos]);
}

// --------------------------------------------- 1) in-degree counts (MLP=2) ----
__global__ void __launch_bounds__(256) k_count(const void* __restrict__ ei) {
    const int base = blockIdx.x * blockDim.x + threadIdx.x;
    const int stride = gridDim.x * blockDim.x;
    const int is64 = detect64((const int*)ei);
    #pragma unroll
    for (int i = 0; i < EPT; i++) {
        int e = base + i * stride;
        if (e < NE) {
            int col = fetch_idx(ei, (long long)NE + e, is64);
            if ((unsigned)col < NN) atomicAdd(&g_cnt[col], 1);
        }
    }
}

// ------------------------------------- 2) block-local inclusive scan ----
__global__ void __launch_bounds__(256) k_scanA() {
    __shared__ int wsum[8];
    const int t = threadIdx.x, lane = t & 31, w = t >> 5;
    const int i = blockIdx.x * 256 + t;
    int c = (i < NN) ? g_cnt[i] : 0;
    if (i < NN) g_cnt[i] = 0;                 // restore zero-invariant
    int incl = c;
    #pragma unroll
    for (int o = 1; o < 32; o <<= 1) {
        int v = __shfl_up_sync(~0u, incl, o);
        if (lane >= o) incl += v;
    }
    if (lane == 31) wsum[w] = incl;
    __syncthreads();
    if (w == 0) {
        int v = (lane < 8) ? wsum[lane] : 0;
        #pragma unroll
        for (int o = 1; o < 8; o <<= 1) {
            int u = __shfl_up_sync(~0u, v, o);
            if (lane >= o) v += u;
        }
        if (lane < 8) wsum[lane] = v;
    }
    __syncthreads();
    incl += (w > 0) ? wsum[w - 1] : 0;
    g_incl[i] = incl;
    if (t == 255) g_bsum[blockIdx.x] = incl;
}

// --------- 3) offsets: each block reduces prior block sums, finalizes ----
__global__ void __launch_bounds__(256) k_scanC() {
    __shared__ int red[8];
    __shared__ int s_boff;
    const int t = threadIdx.x, lane = t & 31, w = t >> 5;
    int v = (t < blockIdx.x) ? g_bsum[t] : 0;   // blockIdx.x <= 195 < 256
    #pragma unroll
    for (int o = 16; o; o >>= 1) v += __shfl_down_sync(~0u, v, o);
    if (lane == 0) red[w] = v;
    __syncthreads();
    if (t == 0) {
        int s = 0;
        #pragma unroll
        for (int k = 0; k < 8; k++) s += red[k];
        s_boff = s;
    }
    __syncthreads();
    const int i = blockIdx.x * 256 + t;
    if (i >= NN) return;
    const int incl = g_incl[i];
    const int excl = (t > 0) ? g_incl[i - 1] : 0;
    const int off  = s_boff + excl;
    const int cnt  = incl - excl;
    g_off[i]  = off;
    g_end[i]  = off + cnt;
    g_cur[i]  = off;
    g_dinv[i] = rsqrtf((float)cnt + 1.0f);          // +1 self loop
}

// ------------------- 4) h = x W^T  (packed FFMA2, fp16 output via smem) ----
// 128 threads = 4 warps; warp w owns nodes [node0+16w,+16) as 8 node-pairs.
// Lane owns channels lane, lane+32, lane+64, lane+96.
__global__ void __launch_bounds__(128) k_gemm(const float* __restrict__ x,
                                              const float* __restrict__ W) {
    extern __shared__ float smem[];
    float* sW  = smem;                       // [128][SW_PITCH]
    float* sxp = smem + CH * SW_PITCH;       // [32 pairs][CH][2]
    __half* sh16 = (__half*)smem;            // reused after mainloop: [64][128]
    const int t = threadIdx.x;
    const int lane = t & 31, wid = t >> 5;
    const int node0 = blockIdx.x * NBT;

    #pragma unroll 8
    for (int o = 0; o < CH; o++)
        sW[o * SW_PITCH + t] = W[o * CH + t];

    #pragma unroll 4
    for (int m = 0; m < NBT; m++) {
        const int node = node0 + m;
        const float v = (node < NN) ? x[(size_t)node * CH + t] : 0.0f;
        sxp[((m >> 1) * CH + t) * 2 + (m & 1)] = v;
    }
    __syncthreads();

    unsigned long long acc2[4][8];
    #pragma unroll
    for (int c = 0; c < 4; c++)
        #pragma unroll
        for (int p = 0; p < 8; p++) acc2[c][p] = 0ull;

    const float* w0 = &sW[lane * SW_PITCH];
    const float* w1 = &sW[(lane + 32) * SW_PITCH];
    const float* w2 = &sW[(lane + 64) * SW_PITCH];
    const float* w3 = &sW[(lane + 96) * SW_PITCH];
    const float* xbase = &sxp[(wid * 8) * CH * 2];

    #pragma unroll 2
    for (int k4 = 0; k4 < CH; k4 += 4) {
        float4 wv[4];
        wv[0] = *(const float4*)(w0 + k4);
        wv[1] = *(const float4*)(w1 + k4);
        wv[2] = *(const float4*)(w2 + k4);
        wv[3] = *(const float4*)(w3 + k4);
        unsigned long long wp[4][4];
        #pragma unroll
        for (int c = 0; c < 4; c++) {
            PACK2(wp[c][0], __float_as_uint(wv[c].x), __float_as_uint(wv[c].x));
            PACK2(wp[c][1], __float_as_uint(wv[c].y), __float_as_uint(wv[c].y));
            PACK2(wp[c][2], __float_as_uint(wv[c].z), __float_as_uint(wv[c].z));
            PACK2(wp[c][3], __float_as_uint(wv[c].w), __float_as_uint(wv[c].w));
        }
        #pragma unroll
        for (int p = 0; p < 8; p++) {
            const float* xb = xbase + (p * CH + k4) * 2;
            ulonglong2 xk01 = *(const ulonglong2*)(xb);
            ulonglong2 xk23 = *(const ulonglong2*)(xb + 4);
            #pragma unroll
            for (int c = 0; c < 4; c++) {
                FMA2(acc2[c][p], xk01.x, wp[c][0], acc2[c][p]);
                FMA2(acc2[c][p], xk01.y, wp[c][1], acc2[c][p]);
                FMA2(acc2[c][p], xk23.x, wp[c][2], acc2[c][p]);
                FMA2(acc2[c][p], xk23.y, wp[c][3], acc2[c][p]);
            }
        }
    }
    __syncthreads();   // done reading sW/sxp; reuse smem as fp16 staging

    // stage h (fp16) in smem: sh16[m][ch], m in [0,64)
    #pragma unroll
    for (int c = 0; c < 4; c++) {
        const int ch = lane + 32 * c;
        #pragma unroll
        for (int p = 0; p < 8; p++) {
            unsigned int lo, hi;
            UNPACK2(lo, hi, acc2[c][p]);
            const int m = wid * 16 + 2 * p;
            sh16[m * CH + ch]       = __float2half_rn(__uint_as_float(lo));
            sh16[(m + 1) * CH + ch] = __float2half_rn(__uint_as_float(hi));
        }
    }
    __syncthreads();

    // coalesced copy smem -> g_hh (64 nodes x 128 ch x 2B = 16KB = 1024 uint4)
    const uint4* s4 = (const uint4*)sh16;
    uint4* d4 = (uint4*)(g_hh + (size_t)node0 * CH);
    #pragma unroll
    for (int i = 0; i < 8; i++) {
        const int u = t + i * 128;              // uint4 index; 16 per node
        const int node = node0 + (u >> 4);
        if (node < NN) d4[u] = s4[u];
    }
}

// ---------------------------------------------- 5) fill CSR lists (MLP=2) ----
__global__ void __launch_bounds__(256) k_fill(const void* __restrict__ ei) {
    const int base = blockIdx.x * blockDim.x + threadIdx.x;
    const int stride = gridDim.x * blockDim.x;
    const int is64 = detect64((const int*)ei);
    #pragma unroll
    for (int i = 0; i < EPT; i++) {
        int e = base + i * stride;
        if (e < NE) {
            int row = fetch_idx(ei, e, is64);
            int col = fetch_idx(ei, (long long)NE + e, is64);
            if ((unsigned)col < NN && (unsigned)row < NN) {
                int pos = atomicAdd(&g_cur[col], 1);
                g_src[pos] = row;
            }
        }
    }
}

// ------------------- 6) gather + fused epilogue (self, norm, bias, silu) ----
// warp per node; lane owns 4 channels (uint2 = 4 fp16); 4-edge unroll
__device__ __forceinline__ void acc_edge(float4& a, uint2 u, float d) {
    float2 f0 = __half22float2(*(const __half2*)&u.x);
    float2 f1 = __half22float2(*(const __half2*)&u.y);
    a.x = fmaf(f0.x, d, a.x);
    a.y = fmaf(f0.y, d, a.y);
    a.z = fmaf(f1.x, d, a.z);
    a.w = fmaf(f1.y, d, a.w);
}

__global__ void __launch_bounds__(256) k_gather(const float* __restrict__ b,
                                                float* __restrict__ out) {
    const int node = (blockIdx.x * blockDim.x + threadIdx.x) >> 5;
    const int lane = threadIdx.x & 31;
    if (node >= NN) return;
    const int c4 = lane * 4;
    const int beg = g_off[node], end = g_end[node];
    const __half* hp = g_hh;

    float4 a0 = make_float4(0.f, 0.f, 0.f, 0.f);
    float4 a1 = make_float4(0.f, 0.f, 0.f, 0.f);
    float4 a2 = make_float4(0.f, 0.f, 0.f, 0.f);
    float4 a3 = make_float4(0.f, 0.f, 0.f, 0.f);
    int e = beg;
    for (; e + 4 <= end; e += 4) {
        const int s0 = __ldg(&g_src[e]);
        const int s1 = __ldg(&g_src[e + 1]);
        const int s2 = __ldg(&g_src[e + 2]);
        const int s3 = __ldg(&g_src[e + 3]);
        const float d0 = __ldg(&g_dinv[s0]);
        const float d1 = __ldg(&g_dinv[s1]);
        const float d2 = __ldg(&g_dinv[s2]);
        const float d3 = __ldg(&g_dinv[s3]);
        uint2 u0 = __ldg((const uint2*)(hp + (size_t)s0 * CH + c4));
        uint2 u1 = __ldg((const uint2*)(hp + (size_t)s1 * CH + c4));
        uint2 u2 = __ldg((const uint2*)(hp + (size_t)s2 * CH + c4));
        uint2 u3 = __ldg((const uint2*)(hp + (size_t)s3 * CH + c4));
        acc_edge(a0, u0, d0);
        acc_edge(a1, u1, d1);
        acc_edge(a2, u2, d2);
        acc_edge(a3, u3, d3);
    }
    for (; e < end; e++) {
        const int s0 = __ldg(&g_src[e]);
        const float d0 = __ldg(&g_dinv[s0]);
        uint2 u0 = __ldg((const uint2*)(hp + (size_t)s0 * CH + c4));
        acc_edge(a0, u0, d0);
    }
    a0.x += a1.x + a2.x + a3.x;
    a0.y += a1.y + a2.y + a3.y;
    a0.z += a1.z + a2.z + a3.z;
    a0.w += a1.w + a2.w + a3.w;

    const float di  = g_dinv[node];
    const float di2 = di * di;
    uint2 us = __ldg((const uint2*)(hp + (size_t)node * CH + c4));
    float2 h0 = __half22float2(*(const __half2*)&us.x);
    float2 h1 = __half22float2(*(const __half2*)&us.y);
    float4 bb = *(const float4*)(b + c4);
    float y;
    y = fmaf(a0.x + h0.x * di, di2, bb.x); a0.x = y / (1.0f + __expf(-y));
    y = fmaf(a0.y + h0.y * di, di2, bb.y); a0.y = y / (1.0f + __expf(-y));
    y = fmaf(a0.z + h1.x * di, di2, bb.z); a0.z = y / (1.0f + __expf(-y));
    y = fmaf(a0.w + h1.y * di, di2, bb.w); a0.w = y / (1.0f + __expf(-y));
    *(float4*)(out + (size_t)node * CH + c4) = a0;
}

// ------------------------------------------------------------------ launch ----
extern "C" void kernel_launch(void* const* d_in, const int* in_sizes, int n_in,
                              void* d_out, int out_size) {
    const float* x  = (const float*)d_in[0];
    const void*  ei = d_in[1];
    const float* W  = (const float*)d_in[2];
    const float* b  = (const float*)d_in[3];
    float* out = (float*)d_out;
    (void)in_sizes; (void)n_in; (void)out_size;

    const int eb = (NE + 256 * EPT - 1) / (256 * EPT);   // 1172 blocks (~1 wave)
    k_count<<<eb, 256>>>(ei);                            // 1
    k_scanA<<<NBLK, 256>>>();                            // 2
    k_scanC<<<NBLK, 256>>>();                            // 3

    const int smem_bytes = (CH * SW_PITCH + (NBT / 2) * CH * 2) * (int)sizeof(float);
    cudaFuncSetAttribute(k_gemm, cudaFuncAttributeMaxDynamicSharedMemorySize, smem_bytes);
    k_gemm<<<(NN + NBT - 1) / NBT, 128, smem_bytes>>>(x, W);  // 4 (ncu capture slot)

    k_fill<<<eb, 256>>>(ei);                             // 5 (needs only scanC)
    k_gather<<<(NN * 32 + 255) / 256, 256>>>(b, out);    // 6
}